// round 1
// baseline (speedup 1.0000x reference)
#include <cuda_runtime.h>
#include <math.h>

#define NN   100000
#define EE   500000
#define TT   8
#define MSGD 64
#define HIDD 64
#define CC   16

// Scratch: per-node aggregated messages (zeroed each launch, atomically accumulated)
__device__ float g_reduced[(size_t)NN * MSGD];

// ---------------------------------------------------------------------------
// Kernel 1: zero the reduction buffer (6.4M floats = 1.6M float4)
// ---------------------------------------------------------------------------
__global__ void zero_kernel() {
    int i = blockIdx.x * blockDim.x + threadIdx.x;
    if (i < NN * MSGD / 4) {
        reinterpret_cast<float4*>(g_reduced)[i] = make_float4(0.f, 0.f, 0.f, 0.f);
    }
}

// ---------------------------------------------------------------------------
// Kernel 2: per-edge message matvec + vectorized atomic scatter
//   msgs[e][m] = sum_h A[type(e)][m][h] * features[src(e)][h]
//   g_reduced[dst(e)][m] += msgs[e][m]
// All 8 type matrices live in SMEM. A_STRIDE pad of 4 floats (16B) makes the
// 8 type base addresses hit 8 distinct 16B groups mod 128B -> LDS.128 with
// mixed per-lane types is conflict-free.
// ---------------------------------------------------------------------------
#define A_STRIDE 4100   // 64*64 + 4 pad floats
#define EDGE_SMEM (TT * A_STRIDE * 4)

__global__ __launch_bounds__(512, 1)
void edge_kernel(const float* __restrict__ features,
                 const float* __restrict__ edge_emb,
                 const int*   __restrict__ etype,
                 const int*   __restrict__ src,
                 const int*   __restrict__ dst) {
    extern __shared__ float A[];
    // Stage all 8 matrices (8*4096 floats) into SMEM, padded layout.
    for (int i = threadIdx.x; i < TT * 1024; i += blockDim.x) {
        int t = i >> 10, j = i & 1023;
        float4 v = reinterpret_cast<const float4*>(edge_emb)[t * 1024 + j];
        float* d = &A[t * A_STRIDE + j * 4];
        d[0] = v.x; d[1] = v.y; d[2] = v.z; d[3] = v.w;
    }
    __syncthreads();

    int e = blockIdx.x * blockDim.x + threadIdx.x;
    if (e >= EE) return;

    int t = etype[e];
    int s = src[e];
    int d = dst[e];

    // Gather source features into registers (16 x float4)
    float4 f4[16];
    const float4* fr = reinterpret_cast<const float4*>(features + (size_t)s * HIDD);
#pragma unroll
    for (int q = 0; q < 16; q++) f4[q] = fr[q];

    const float* At   = &A[t * A_STRIDE];
    float*       outp = g_reduced + (size_t)d * MSGD;

#pragma unroll 1
    for (int m = 0; m < MSGD; m += 4) {
        const float4* r0 = reinterpret_cast<const float4*>(At + (m + 0) * 64);
        const float4* r1 = reinterpret_cast<const float4*>(At + (m + 1) * 64);
        const float4* r2 = reinterpret_cast<const float4*>(At + (m + 2) * 64);
        const float4* r3 = reinterpret_cast<const float4*>(At + (m + 3) * 64);
        float a0 = 0.f, a1 = 0.f, a2 = 0.f, a3 = 0.f;
#pragma unroll
        for (int q = 0; q < 16; q++) {
            float4 fv = f4[q];
            float4 w;
            w = r0[q]; a0 += w.x * fv.x + w.y * fv.y + w.z * fv.z + w.w * fv.w;
            w = r1[q]; a1 += w.x * fv.x + w.y * fv.y + w.z * fv.z + w.w * fv.w;
            w = r2[q]; a2 += w.x * fv.x + w.y * fv.y + w.z * fv.z + w.w * fv.w;
            w = r3[q]; a3 += w.x * fv.x + w.y * fv.y + w.z * fv.z + w.w * fv.w;
        }
        // Vectorized reduction (sm_90+): one 16B atomic instead of 4 scalar ones.
        asm volatile("red.global.add.v4.f32 [%0], {%1, %2, %3, %4};"
                     :: "l"(outp + m), "f"(a0), "f"(a1), "f"(a2), "f"(a3)
                     : "memory");
    }
}

// ---------------------------------------------------------------------------
// Kernel 3: fused GRU step + output projection, lane-per-node.
//   gi = reduced @ W_ih^T + b_ih ; gh = h @ W_hh^T + b_hh
//   r = sig(i_r+h_r); z = sig(i_z+h_z); n = tanh(i_n + r*h_n)
//   h' = (1-z)*n + z*h ;  out = h' @ W_out^T + b_out
// Weights (2x 192x64) + W_out^T + biases in SMEM (broadcast reads).
// ---------------------------------------------------------------------------
#define NODE_SMEM (26000 * 4)

__device__ __forceinline__ float sigm(float x) { return 1.f / (1.f + expf(-x)); }

__global__ __launch_bounds__(256, 1)
void node_kernel(const float* __restrict__ features,
                 const float* __restrict__ W_ih, const float* __restrict__ W_hh,
                 const float* __restrict__ b_ih, const float* __restrict__ b_hh,
                 const float* __restrict__ W_out, const float* __restrict__ b_out,
                 float* __restrict__ out) {
    extern __shared__ float sm[];
    float* sWih  = sm;            // 192*64 = 12288
    float* sWhh  = sm + 12288;    // 12288
    float* sWoT  = sm + 24576;    // [64][16] transposed W_out = 1024
    float* sbih  = sm + 25600;    // 192
    float* sbhh  = sm + 25792;    // 192
    float* sbout = sm + 25984;    // 16

    {
        float4* d1 = reinterpret_cast<float4*>(sWih);
        const float4* s1 = reinterpret_cast<const float4*>(W_ih);
        for (int i = threadIdx.x; i < 3072; i += blockDim.x) d1[i] = s1[i];
        float4* d2 = reinterpret_cast<float4*>(sWhh);
        const float4* s2 = reinterpret_cast<const float4*>(W_hh);
        for (int i = threadIdx.x; i < 3072; i += blockDim.x) d2[i] = s2[i];
        for (int i = threadIdx.x; i < CC * 64; i += blockDim.x) {
            int c = i / 64, j = i % 64;
            sWoT[j * CC + c] = W_out[i];
        }
        for (int i = threadIdx.x; i < 192; i += blockDim.x) {
            sbih[i] = b_ih[i];
            sbhh[i] = b_hh[i];
        }
        if (threadIdx.x < CC) sbout[threadIdx.x] = b_out[threadIdx.x];
    }
    __syncthreads();

    int n = blockIdx.x * blockDim.x + threadIdx.x;
    if (n >= NN) return;

    float4 h4[16], r4[16];
    const float4* hp = reinterpret_cast<const float4*>(features + (size_t)n * HIDD);
    const float4* rp = reinterpret_cast<const float4*>(g_reduced + (size_t)n * MSGD);
#pragma unroll
    for (int q = 0; q < 16; q++) { h4[q] = hp[q]; r4[q] = rp[q]; }

    float oacc[CC];
#pragma unroll
    for (int c = 0; c < CC; c++) oacc[c] = sbout[c];

#pragma unroll 1
    for (int jq = 0; jq < 16; jq++) {
        float4 hjv = h4[jq];
#pragma unroll
        for (int dj = 0; dj < 4; dj++) {
            int j = jq * 4 + dj;
            float ir = sbih[j], iz = sbih[64 + j], inn = sbih[128 + j];
            float hr = sbhh[j], hz = sbhh[64 + j], hn  = sbhh[128 + j];
            const float4* wir = reinterpret_cast<const float4*>(sWih + (j      ) * 64);
            const float4* wiz = reinterpret_cast<const float4*>(sWih + (64  + j) * 64);
            const float4* win = reinterpret_cast<const float4*>(sWih + (128 + j) * 64);
            const float4* whr = reinterpret_cast<const float4*>(sWhh + (j      ) * 64);
            const float4* whz = reinterpret_cast<const float4*>(sWhh + (64  + j) * 64);
            const float4* whn = reinterpret_cast<const float4*>(sWhh + (128 + j) * 64);
#pragma unroll
            for (int q = 0; q < 16; q++) {
                float4 rv = r4[q], hv = h4[q], w;
                w = wir[q]; ir  += w.x * rv.x + w.y * rv.y + w.z * rv.z + w.w * rv.w;
                w = wiz[q]; iz  += w.x * rv.x + w.y * rv.y + w.z * rv.z + w.w * rv.w;
                w = win[q]; inn += w.x * rv.x + w.y * rv.y + w.z * rv.z + w.w * rv.w;
                w = whr[q]; hr  += w.x * hv.x + w.y * hv.y + w.z * hv.z + w.w * hv.w;
                w = whz[q]; hz  += w.x * hv.x + w.y * hv.y + w.z * hv.z + w.w * hv.w;
                w = whn[q]; hn  += w.x * hv.x + w.y * hv.y + w.z * hv.z + w.w * hv.w;
            }
            float rg = sigm(ir + hr);
            float zg = sigm(iz + hz);
            float ng = tanhf(inn + rg * hn);
            float hj = (dj == 0) ? hjv.x : (dj == 1) ? hjv.y : (dj == 2) ? hjv.z : hjv.w;
            float hnew = (1.f - zg) * ng + zg * hj;
            const float* wo = sWoT + j * CC;
#pragma unroll
            for (int c = 0; c < CC; c++) oacc[c] += wo[c] * hnew;
        }
    }

    float4* op = reinterpret_cast<float4*>(out + (size_t)n * CC);
#pragma unroll
    for (int q = 0; q < 4; q++) {
        op[q] = make_float4(oacc[4 * q + 0], oacc[4 * q + 1],
                            oacc[4 * q + 2], oacc[4 * q + 3]);
    }
}

// ---------------------------------------------------------------------------
extern "C" void kernel_launch(void* const* d_in, const int* in_sizes, int n_in,
                              void* d_out, int out_size) {
    const float* features = (const float*)d_in[0];
    const float* edge_emb = (const float*)d_in[1];
    const float* W_ih     = (const float*)d_in[2];
    const float* W_hh     = (const float*)d_in[3];
    const float* b_ih     = (const float*)d_in[4];
    const float* b_hh     = (const float*)d_in[5];
    const float* W_out    = (const float*)d_in[6];
    const float* b_out    = (const float*)d_in[7];
    const int*   etype    = (const int*)d_in[8];
    const int*   src      = (const int*)d_in[9];
    const int*   dst      = (const int*)d_in[10];
    float*       out      = (float*)d_out;

    cudaFuncSetAttribute(edge_kernel, cudaFuncAttributeMaxDynamicSharedMemorySize, EDGE_SMEM);
    cudaFuncSetAttribute(node_kernel, cudaFuncAttributeMaxDynamicSharedMemorySize, NODE_SMEM);

    zero_kernel<<<(NN * MSGD / 4 + 255) / 256, 256>>>();
    edge_kernel<<<(EE + 511) / 512, 512, EDGE_SMEM>>>(features, edge_emb, etype, src, dst);
    node_kernel<<<(NN + 255) / 256, 256, NODE_SMEM>>>(features, W_ih, W_hh,
                                                      b_ih, b_hh, W_out, b_out, out);
}

// round 2
// speedup vs baseline: 1.5556x; 1.5556x over previous
#include <cuda_runtime.h>
#include <math.h>

#define NN   100000
#define EE   500000
#define TT   8
#define MSGD 64
#define HIDD 64
#define CC   16

typedef unsigned long long ull;

// ---------------------------------------------------------------------------
// Device scratch
// ---------------------------------------------------------------------------
__device__ __align__(16) float g_reduced[(size_t)NN * MSGD];
__device__ int g_counts[TT];
__device__ int g_bases[TT + 1];
__device__ int g_cursor[TT];
__device__ int g_src_s[EE];
__device__ int g_dst_s[EE];

// ---------------------------------------------------------------------------
// Packed fp32x2 helpers (Blackwell FFMA2 — 2x fp32 FMA per instruction)
// ---------------------------------------------------------------------------
__device__ __forceinline__ void fma2(ull& d, ull a, ull b) {
    asm volatile("fma.rn.f32x2 %0, %1, %2, %0;" : "+l"(d) : "l"(a), "l"(b));
}
__device__ __forceinline__ float2 asf2(ull v) {
    float2 r;
    asm("mov.b64 {%0, %1}, %2;" : "=f"(r.x), "=f"(r.y) : "l"(v));
    return r;
}
__device__ __forceinline__ float sigm(float x) { return 1.f / (1.f + expf(-x)); }

// ---------------------------------------------------------------------------
// Kernel 0: zero reduction buffer + type counters
// ---------------------------------------------------------------------------
__global__ void zero_kernel() {
    int i = blockIdx.x * blockDim.x + threadIdx.x;
    if (i < NN * MSGD / 4) {
        reinterpret_cast<float4*>(g_reduced)[i] = make_float4(0.f, 0.f, 0.f, 0.f);
    }
    if (blockIdx.x == 0 && threadIdx.x < TT) g_counts[threadIdx.x] = 0;
}

// ---------------------------------------------------------------------------
// Kernel 1: per-block histogram of edge types
// ---------------------------------------------------------------------------
__global__ void hist_kernel(const int* __restrict__ etype) {
    __shared__ int h[TT];
    if (threadIdx.x < TT) h[threadIdx.x] = 0;
    __syncthreads();
    int e = blockIdx.x * blockDim.x + threadIdx.x;
    if (e < EE) atomicAdd(&h[etype[e]], 1);
    __syncthreads();
    if (threadIdx.x < TT) atomicAdd(&g_counts[threadIdx.x], h[threadIdx.x]);
}

// ---------------------------------------------------------------------------
// Kernel 2: tiny exclusive scan (8 values)
// ---------------------------------------------------------------------------
__global__ void scan_kernel() {
    if (threadIdx.x == 0) {
        int b = 0;
        for (int t = 0; t < TT; t++) {
            g_bases[t] = b;
            g_cursor[t] = b;
            b += g_counts[t];
        }
        g_bases[TT] = b;
    }
}

// ---------------------------------------------------------------------------
// Kernel 3: bin edges by type (block-aggregated cursors; order within a
// bucket is irrelevant — scatter-add is order independent)
// ---------------------------------------------------------------------------
__global__ void scatter_kernel(const int* __restrict__ etype,
                               const int* __restrict__ src,
                               const int* __restrict__ dst) {
    __shared__ int h[TT], base[TT], h2[TT];
    int e = blockIdx.x * blockDim.x + threadIdx.x;
    if (threadIdx.x < TT) { h[threadIdx.x] = 0; h2[threadIdx.x] = 0; }
    __syncthreads();
    int t = 0, s = 0, d = 0;
    bool valid = (e < EE);
    if (valid) {
        t = etype[e]; s = src[e]; d = dst[e];
        atomicAdd(&h[t], 1);
    }
    __syncthreads();
    if (threadIdx.x < TT)
        base[threadIdx.x] = atomicAdd(&g_cursor[threadIdx.x], h[threadIdx.x]);
    __syncthreads();
    if (valid) {
        int pos = base[t] + atomicAdd(&h2[t], 1);
        g_src_s[pos] = s;
        g_dst_s[pos] = d;
    }
}

// ---------------------------------------------------------------------------
// Kernel 4: edge messages. Edges sorted by type; each warp holds its type's
// 64x64 matrix in registers (2 rows/lane). Source features stream via a
// cp.async ring; FFMA2 compute; red.v2 scatter.
// ---------------------------------------------------------------------------
#define EBLOCKS 148
#define ETHREADS 256
#define NWARP   (EBLOCKS * ETHREADS / 32)              // 1184
#define CHUNK   ((EE + NWARP - 1) / NWARP)             // 423

__global__ void __launch_bounds__(ETHREADS, 1)
edge_kernel(const float* __restrict__ features,
            const float* __restrict__ edge_emb) {
    __shared__ float4 sf[ETHREADS / 32][8][16];        // 8-slot ring per warp
    const unsigned FULL = 0xffffffffu;
    const int wib = threadIdx.x >> 5, lane = threadIdx.x & 31;

    int w = blockIdx.x * (ETHREADS / 32) + wib;
    long e0 = (long)w * CHUNK;
    if (e0 >= EE) return;
    long e1 = e0 + CHUNK;
    if (e1 > EE) e1 = EE;

    int bases[TT + 1];
#pragma unroll
    for (int i = 0; i <= TT; i++) bases[i] = g_bases[i];

    ull wA[32], wB[32];  // rows 2*lane and 2*lane+1 of current type matrix
    long e = e0;
    int t = 0;
    while (e < e1) {
        while (bases[t + 1] <= e) t++;
        long seg_end = bases[t + 1] < e1 ? bases[t + 1] : e1;

        // Load matrix for type t into registers
        {
            const ulonglong2* pA = reinterpret_cast<const ulonglong2*>(
                edge_emb + (size_t)t * 4096 + (size_t)(2 * lane) * 64);
            const ulonglong2* pB = reinterpret_cast<const ulonglong2*>(
                edge_emb + (size_t)t * 4096 + (size_t)(2 * lane + 1) * 64);
#pragma unroll
            for (int q = 0; q < 16; q++) {
                ulonglong2 a = pA[q]; wA[2 * q] = a.x; wA[2 * q + 1] = a.y;
            }
#pragma unroll
            for (int q = 0; q < 16; q++) {
                ulonglong2 b = pB[q]; wB[2 * q] = b.x; wB[2 * q + 1] = b.y;
            }
        }

        for (long b0 = e; b0 < seg_end; b0 += 32) {
            int nb = (int)((seg_end - b0 < 32) ? (seg_end - b0) : 32);
            int my_s = 0, my_d = 0;
            if (lane < nb) {
                my_s = g_src_s[b0 + lane];
                my_d = g_dst_s[b0 + lane];
            }
            // Prologue: prefetch edges 0..2
#pragma unroll
            for (int j = 0; j < 3; j++) {
                if (j < nb) {
                    int s = __shfl_sync(FULL, my_s, j);
                    if (lane < 16) {
                        unsigned sp = (unsigned)__cvta_generic_to_shared(
                            &sf[wib][j & 7][lane]);
                        asm volatile("cp.async.ca.shared.global [%0], [%1], 16;"
                                     :: "r"(sp),
                                        "l"(features + (size_t)s * 64 + lane * 4));
                    }
                }
                asm volatile("cp.async.commit_group;");
            }
            for (int j = 0; j < nb; j++) {
                asm volatile("cp.async.wait_group 2;");
                __syncwarp();
                // Prefetch edge j+3 (slot distance 3 < ring 8, skew-safe)
                if (j + 3 < nb) {
                    int s = __shfl_sync(FULL, my_s, j + 3);
                    if (lane < 16) {
                        unsigned sp = (unsigned)__cvta_generic_to_shared(
                            &sf[wib][(j + 3) & 7][lane]);
                        asm volatile("cp.async.ca.shared.global [%0], [%1], 16;"
                                     :: "r"(sp),
                                        "l"(features + (size_t)s * 64 + lane * 4));
                    }
                }
                asm volatile("cp.async.commit_group;");

                int d = __shfl_sync(FULL, my_d, j);
                const ulonglong2* fp = reinterpret_cast<const ulonglong2*>(
                    &sf[wib][j & 7][0]);
                ull a0 = 0, a1 = 0, c0 = 0, c1 = 0;
#pragma unroll
                for (int q = 0; q < 16; q += 2) {
                    ulonglong2 f0 = fp[q], f1 = fp[q + 1];
                    fma2(a0, wA[2 * q],     f0.x); fma2(a0, wA[2 * q + 1], f0.y);
                    fma2(c0, wB[2 * q],     f0.x); fma2(c0, wB[2 * q + 1], f0.y);
                    fma2(a1, wA[2 * q + 2], f1.x); fma2(a1, wA[2 * q + 3], f1.y);
                    fma2(c1, wB[2 * q + 2], f1.x); fma2(c1, wB[2 * q + 3], f1.y);
                }
                float2 fa0 = asf2(a0), fa1 = asf2(a1);
                float2 fc0 = asf2(c0), fc1 = asf2(c1);
                float r0 = (fa0.x + fa0.y) + (fa1.x + fa1.y);
                float r1 = (fc0.x + fc0.y) + (fc1.x + fc1.y);
                const float* op = g_reduced + (size_t)d * 64 + 2 * lane;
                asm volatile("red.global.add.v2.f32 [%0], {%1, %2};"
                             :: "l"(op), "f"(r0), "f"(r1) : "memory");
            }
            asm volatile("cp.async.wait_group 0;");
            __syncwarp();
        }
        e = seg_end;
    }
}

// ---------------------------------------------------------------------------
// Kernel 5: fused GRU + output projection, FFMA2 throughout.
// ---------------------------------------------------------------------------
#define NODE_SMEM (26000 * 4)

__global__ void __launch_bounds__(256, 1)
node_kernel(const float* __restrict__ features,
            const float* __restrict__ W_ih, const float* __restrict__ W_hh,
            const float* __restrict__ b_ih, const float* __restrict__ b_hh,
            const float* __restrict__ W_out, const float* __restrict__ b_out,
            float* __restrict__ out) {
    extern __shared__ float sm[];
    float* sWih  = sm;            // 12288
    float* sWhh  = sm + 12288;    // 12288
    float* sWoT  = sm + 24576;    // 1024  (transposed W_out [64][16])
    float* sbih  = sm + 25600;    // 192
    float* sbhh  = sm + 25792;    // 192
    float* sbout = sm + 25984;    // 16

    {
        float4* d1 = reinterpret_cast<float4*>(sWih);
        const float4* s1 = reinterpret_cast<const float4*>(W_ih);
        for (int i = threadIdx.x; i < 3072; i += blockDim.x) d1[i] = s1[i];
        float4* d2 = reinterpret_cast<float4*>(sWhh);
        const float4* s2 = reinterpret_cast<const float4*>(W_hh);
        for (int i = threadIdx.x; i < 3072; i += blockDim.x) d2[i] = s2[i];
        for (int i = threadIdx.x; i < CC * 64; i += blockDim.x) {
            int c = i / 64, j = i % 64;
            sWoT[j * CC + c] = W_out[i];
        }
        for (int i = threadIdx.x; i < 192; i += blockDim.x) {
            sbih[i] = b_ih[i];
            sbhh[i] = b_hh[i];
        }
        if (threadIdx.x < CC) sbout[threadIdx.x] = b_out[threadIdx.x];
    }
    __syncthreads();

    int n = blockIdx.x * blockDim.x + threadIdx.x;
    if (n >= NN) return;

    ulonglong2 hh[16], rr[16];
    const ulonglong2* hp = reinterpret_cast<const ulonglong2*>(features + (size_t)n * 64);
    const ulonglong2* rp = reinterpret_cast<const ulonglong2*>(g_reduced + (size_t)n * 64);
#pragma unroll
    for (int q = 0; q < 16; q++) { hh[q] = hp[q]; rr[q] = rp[q]; }

    ull oacc[8];
    const ulonglong2* bo = reinterpret_cast<const ulonglong2*>(sbout);
#pragma unroll
    for (int i = 0; i < 4; i++) {
        ulonglong2 v = bo[i];
        oacc[2 * i] = v.x; oacc[2 * i + 1] = v.y;
    }

#pragma unroll 1
    for (int jq = 0; jq < 16; jq++) {
#pragma unroll
        for (int dj = 0; dj < 4; dj++) {
            int j = jq * 4 + dj;
            ull air = 0, aiz = 0, ain = 0, ahr = 0, ahz = 0, ahn = 0;
            const ulonglong2* wir = reinterpret_cast<const ulonglong2*>(sWih + (j      ) * 64);
            const ulonglong2* wiz = reinterpret_cast<const ulonglong2*>(sWih + (64  + j) * 64);
            const ulonglong2* win = reinterpret_cast<const ulonglong2*>(sWih + (128 + j) * 64);
            const ulonglong2* whr = reinterpret_cast<const ulonglong2*>(sWhh + (j      ) * 64);
            const ulonglong2* whz = reinterpret_cast<const ulonglong2*>(sWhh + (64  + j) * 64);
            const ulonglong2* whn = reinterpret_cast<const ulonglong2*>(sWhh + (128 + j) * 64);
#pragma unroll
            for (int q = 0; q < 16; q++) {
                ulonglong2 rv = rr[q], hv = hh[q], w;
                w = wir[q]; fma2(air, w.x, rv.x); fma2(air, w.y, rv.y);
                w = wiz[q]; fma2(aiz, w.x, rv.x); fma2(aiz, w.y, rv.y);
                w = win[q]; fma2(ain, w.x, rv.x); fma2(ain, w.y, rv.y);
                w = whr[q]; fma2(ahr, w.x, hv.x); fma2(ahr, w.y, hv.y);
                w = whz[q]; fma2(ahz, w.x, hv.x); fma2(ahz, w.y, hv.y);
                w = whn[q]; fma2(ahn, w.x, hv.x); fma2(ahn, w.y, hv.y);
            }
            float2 v;
            v = asf2(air); float ir  = v.x + v.y + sbih[j];
            v = asf2(aiz); float iz  = v.x + v.y + sbih[64 + j];
            v = asf2(ain); float inn = v.x + v.y + sbih[128 + j];
            v = asf2(ahr); float hr  = v.x + v.y + sbhh[j];
            v = asf2(ahz); float hz  = v.x + v.y + sbhh[64 + j];
            v = asf2(ahn); float hn  = v.x + v.y + sbhh[128 + j];
            float rg = sigm(ir + hr);
            float zg = sigm(iz + hz);
            float ng = tanhf(inn + rg * hn);
            float2 hjp = asf2((dj & 2) ? hh[jq].y : hh[jq].x);
            float hj = (dj & 1) ? hjp.y : hjp.x;
            float hnew = (1.f - zg) * ng + zg * hj;
            ull hn2;
            asm("mov.b64 %0, {%1, %1};" : "=l"(hn2) : "f"(hnew));
            const ulonglong2* wo = reinterpret_cast<const ulonglong2*>(sWoT + j * CC);
#pragma unroll
            for (int c = 0; c < 4; c++) {
                ulonglong2 wv = wo[c];
                fma2(oacc[2 * c], wv.x, hn2);
                fma2(oacc[2 * c + 1], wv.y, hn2);
            }
        }
    }

    ulonglong2* op = reinterpret_cast<ulonglong2*>(out + (size_t)n * CC);
#pragma unroll
    for (int i = 0; i < 4; i++) {
        ulonglong2 v;
        v.x = oacc[2 * i]; v.y = oacc[2 * i + 1];
        op[i] = v;
    }
}

// ---------------------------------------------------------------------------
extern "C" void kernel_launch(void* const* d_in, const int* in_sizes, int n_in,
                              void* d_out, int out_size) {
    const float* features = (const float*)d_in[0];
    const float* edge_emb = (const float*)d_in[1];
    const float* W_ih     = (const float*)d_in[2];
    const float* W_hh     = (const float*)d_in[3];
    const float* b_ih     = (const float*)d_in[4];
    const float* b_hh     = (const float*)d_in[5];
    const float* W_out    = (const float*)d_in[6];
    const float* b_out    = (const float*)d_in[7];
    const int*   etype    = (const int*)d_in[8];
    const int*   src      = (const int*)d_in[9];
    const int*   dst      = (const int*)d_in[10];
    float*       out      = (float*)d_out;

    cudaFuncSetAttribute(node_kernel, cudaFuncAttributeMaxDynamicSharedMemorySize, NODE_SMEM);

    zero_kernel<<<(NN * MSGD / 4 + 255) / 256, 256>>>();
    hist_kernel<<<(EE + 511) / 512, 512>>>(etype);
    scan_kernel<<<1, 32>>>();
    scatter_kernel<<<(EE + 511) / 512, 512>>>(etype, src, dst);
    edge_kernel<<<EBLOCKS, ETHREADS>>>(features, edge_emb);
    node_kernel<<<(NN + 255) / 256, 256, NODE_SMEM>>>(features, W_ih, W_hh,
                                                      b_ih, b_hh, W_out, b_out, out);
}

// round 4
// speedup vs baseline: 1.6024x; 1.0300x over previous
#include <cuda_runtime.h>
#include <math.h>

#define NN   100000
#define EE   500000
#define TT   8
#define MSGD 64
#define HIDD 64
#define CC   16

typedef unsigned long long ull;

// ---------------------------------------------------------------------------
// Device scratch
// ---------------------------------------------------------------------------
__device__ __align__(16) float g_reduced[(size_t)NN * MSGD];
__device__ int g_counts[TT];
__device__ int g_cursor[TT];
__device__ int g_src_s[EE];
__device__ int g_dst_s[EE];

// ---------------------------------------------------------------------------
// Packed fp32x2 helpers (Blackwell FFMA2)
// ---------------------------------------------------------------------------
__device__ __forceinline__ void fma2(ull& d, ull a, ull b) {
    asm volatile("fma.rn.f32x2 %0, %1, %2, %0;" : "+l"(d) : "l"(a), "l"(b));
}
__device__ __forceinline__ float2 asf2(ull v) {
    float2 r;
    asm("mov.b64 {%0, %1}, %2;" : "=f"(r.x), "=f"(r.y) : "l"(v));
    return r;
}
__device__ __forceinline__ float sigm(float x) { return 1.f / (1.f + expf(-x)); }

// ---------------------------------------------------------------------------
// Kernel 0: zero reduction buffer + reset counters.
// Counter reset MUST be in a separate launch from the histogram adds —
// the launch boundary is the only grid-wide ordering point.
// ---------------------------------------------------------------------------
__global__ void zero_kernel() {
    int i = blockIdx.x * blockDim.x + threadIdx.x;
    if (i < NN * MSGD / 4) {
        reinterpret_cast<float4*>(g_reduced)[i] = make_float4(0.f, 0.f, 0.f, 0.f);
    }
    if (blockIdx.x == 0 && threadIdx.x < TT) {
        g_counts[threadIdx.x] = 0;
        g_cursor[threadIdx.x] = 0;
    }
}

// ---------------------------------------------------------------------------
// Kernel 1: per-block histogram of edge types
// ---------------------------------------------------------------------------
__global__ void hist_kernel(const int* __restrict__ etype) {
    __shared__ int h[TT];
    if (threadIdx.x < TT) h[threadIdx.x] = 0;
    __syncthreads();
    int e = blockIdx.x * blockDim.x + threadIdx.x;
    if (e < EE) atomicAdd(&h[etype[e]], 1);
    __syncthreads();
    if (threadIdx.x < TT) atomicAdd(&g_counts[threadIdx.x], h[threadIdx.x]);
}

// ---------------------------------------------------------------------------
// Kernel 2: bin edges by type. Bases derived from g_counts (final after the
// hist launch retires) by a local 8-element prefix — no scan kernel needed.
// ---------------------------------------------------------------------------
__global__ void scatter_kernel(const int* __restrict__ etype,
                               const int* __restrict__ src,
                               const int* __restrict__ dst) {
    __shared__ int h[TT], base[TT], h2[TT];
    int e = blockIdx.x * blockDim.x + threadIdx.x;
    if (threadIdx.x < TT) { h[threadIdx.x] = 0; h2[threadIdx.x] = 0; }
    __syncthreads();
    int t = 0, s = 0, d = 0;
    bool valid = (e < EE);
    if (valid) {
        t = etype[e]; s = src[e]; d = dst[e];
        atomicAdd(&h[t], 1);
    }
    __syncthreads();
    if (threadIdx.x < TT) {
        int b = 0;
#pragma unroll
        for (int q = 0; q < TT; q++) {
            int c = g_counts[q];
            if (q < (int)threadIdx.x) b += c;
        }
        base[threadIdx.x] = b + atomicAdd(&g_cursor[threadIdx.x], h[threadIdx.x]);
    }
    __syncthreads();
    if (valid) {
        int pos = base[t] + atomicAdd(&h2[t], 1);
        g_src_s[pos] = s;
        g_dst_s[pos] = d;
    }
}

// ---------------------------------------------------------------------------
// Kernel 3: edge messages. Sorted by type; matrix in registers (2 rows/lane);
// cp.async ring depth 6; pair-lane red.v4 scatter (8M LTS atomic ops).
// ---------------------------------------------------------------------------
#define EBLOCKS 148
#define ETHREADS 256
#define NWARP   (EBLOCKS * ETHREADS / 32)              // 1184
#define CHUNK   ((EE + NWARP - 1) / NWARP)             // 423

__global__ void __launch_bounds__(ETHREADS, 1)
edge_kernel(const float* __restrict__ features,
            const float* __restrict__ edge_emb) {
    __shared__ float4 sf[ETHREADS / 32][8][16];        // 8-slot ring per warp
    const unsigned FULL = 0xffffffffu;
    const int wib = threadIdx.x >> 5, lane = threadIdx.x & 31;

    int w = blockIdx.x * (ETHREADS / 32) + wib;
    long e0 = (long)w * CHUNK;
    if (e0 >= EE) return;
    long e1 = e0 + CHUNK;
    if (e1 > EE) e1 = EE;

    int bases[TT + 1];
    {
        int b = 0;
#pragma unroll
        for (int t = 0; t < TT; t++) { bases[t] = b; b += g_counts[t]; }
        bases[TT] = b;
    }

    ull wA[32], wB[32];  // rows 2*lane, 2*lane+1 of current type matrix
    long e = e0;
    int t = 0;
    while (e < e1) {
        while (bases[t + 1] <= e) t++;
        long seg_end = bases[t + 1] < e1 ? bases[t + 1] : e1;

        {
            const ulonglong2* pA = reinterpret_cast<const ulonglong2*>(
                edge_emb + (size_t)t * 4096 + (size_t)(2 * lane) * 64);
            const ulonglong2* pB = reinterpret_cast<const ulonglong2*>(
                edge_emb + (size_t)t * 4096 + (size_t)(2 * lane + 1) * 64);
#pragma unroll
            for (int q = 0; q < 16; q++) {
                ulonglong2 a = pA[q]; wA[2 * q] = a.x; wA[2 * q + 1] = a.y;
            }
#pragma unroll
            for (int q = 0; q < 16; q++) {
                ulonglong2 b = pB[q]; wB[2 * q] = b.x; wB[2 * q + 1] = b.y;
            }
        }

        for (long b0 = e; b0 < seg_end; b0 += 32) {
            int nb = (int)((seg_end - b0 < 32) ? (seg_end - b0) : 32);
            int my_s = 0, my_d = 0;
            if (lane < nb) {
                my_s = g_src_s[b0 + lane];
                my_d = g_dst_s[b0 + lane];
            }
            // Prologue: prefetch edges 0..5 (depth 6 of 8-slot ring)
#pragma unroll
            for (int j = 0; j < 6; j++) {
                if (j < nb) {
                    int s = __shfl_sync(FULL, my_s, j);
                    if (lane < 16) {
                        unsigned sp = (unsigned)__cvta_generic_to_shared(
                            &sf[wib][j & 7][lane]);
                        asm volatile("cp.async.cg.shared.global [%0], [%1], 16;"
                                     :: "r"(sp),
                                        "l"(features + (size_t)s * 64 + lane * 4));
                    }
                }
                asm volatile("cp.async.commit_group;");
            }
            for (int j = 0; j < nb; j++) {
                asm volatile("cp.async.wait_group 5;");
                __syncwarp();
                if (j + 6 < nb) {
                    int s = __shfl_sync(FULL, my_s, j + 6);
                    if (lane < 16) {
                        unsigned sp = (unsigned)__cvta_generic_to_shared(
                            &sf[wib][(j + 6) & 7][lane]);
                        asm volatile("cp.async.cg.shared.global [%0], [%1], 16;"
                                     :: "r"(sp),
                                        "l"(features + (size_t)s * 64 + lane * 4));
                    }
                }
                asm volatile("cp.async.commit_group;");

                int d = __shfl_sync(FULL, my_d, j);
                const ulonglong2* fp = reinterpret_cast<const ulonglong2*>(
                    &sf[wib][j & 7][0]);
                ull a0 = 0, a1 = 0, c0 = 0, c1 = 0;
#pragma unroll
                for (int q = 0; q < 16; q += 2) {
                    ulonglong2 f0 = fp[q], f1 = fp[q + 1];
                    fma2(a0, wA[2 * q],     f0.x); fma2(a0, wA[2 * q + 1], f0.y);
                    fma2(c0, wB[2 * q],     f0.x); fma2(c0, wB[2 * q + 1], f0.y);
                    fma2(a1, wA[2 * q + 2], f1.x); fma2(a1, wA[2 * q + 3], f1.y);
                    fma2(c1, wB[2 * q + 2], f1.x); fma2(c1, wB[2 * q + 3], f1.y);
                }
                float2 fa0 = asf2(a0), fa1 = asf2(a1);
                float2 fc0 = asf2(c0), fc1 = asf2(c1);
                float r0 = (fa0.x + fa0.y) + (fa1.x + fa1.y);   // dim 2*lane
                float r1 = (fc0.x + fc0.y) + (fc1.x + fc1.y);   // dim 2*lane+1
                // Pair lanes (2k, 2k+1): even lane issues red.v4 for dims 4k..4k+3
                float p0 = __shfl_xor_sync(FULL, r0, 1);
                float p1 = __shfl_xor_sync(FULL, r1, 1);
                if (!(lane & 1)) {
                    const float* op = g_reduced + (size_t)d * 64 + 2 * lane;
                    asm volatile("red.global.add.v4.f32 [%0], {%1, %2, %3, %4};"
                                 :: "l"(op), "f"(r0), "f"(r1), "f"(p0), "f"(p1)
                                 : "memory");
                }
            }
            asm volatile("cp.async.wait_group 0;");
            __syncwarp();
        }
        e = seg_end;
    }
}

// ---------------------------------------------------------------------------
// Kernel 4: fused GRU + out projection. Persistent (148 blocks), FFMA2.
// ---------------------------------------------------------------------------
#define NODE_SMEM (26000 * 4)
#define NBLOCKS 148
#define NTHREADS 256

__global__ void __launch_bounds__(NTHREADS, 1)
node_kernel(const float* __restrict__ features,
            const float* __restrict__ W_ih, const float* __restrict__ W_hh,
            const float* __restrict__ b_ih, const float* __restrict__ b_hh,
            const float* __restrict__ W_out, const float* __restrict__ b_out,
            float* __restrict__ out) {
    extern __shared__ float sm[];
    float* sWih  = sm;            // 12288
    float* sWhh  = sm + 12288;    // 12288
    float* sWoT  = sm + 24576;    // 1024 (W_out transposed [64][16])
    float* sbih  = sm + 25600;    // 192
    float* sbhh  = sm + 25792;    // 192
    float* sbout = sm + 25984;    // 16

    {
        float4* d1 = reinterpret_cast<float4*>(sWih);
        const float4* s1 = reinterpret_cast<const float4*>(W_ih);
        for (int i = threadIdx.x; i < 3072; i += blockDim.x) d1[i] = s1[i];
        float4* d2 = reinterpret_cast<float4*>(sWhh);
        const float4* s2 = reinterpret_cast<const float4*>(W_hh);
        for (int i = threadIdx.x; i < 3072; i += blockDim.x) d2[i] = s2[i];
        for (int i = threadIdx.x; i < CC * 64; i += blockDim.x) {
            int c = i / 64, j = i % 64;
            sWoT[j * CC + c] = W_out[i];
        }
        for (int i = threadIdx.x; i < 192; i += blockDim.x) {
            sbih[i] = b_ih[i];
            sbhh[i] = b_hh[i];
        }
        if (threadIdx.x < CC) sbout[threadIdx.x] = b_out[threadIdx.x];
    }
    __syncthreads();

    for (int n = blockIdx.x * NTHREADS + threadIdx.x; n < NN;
         n += NBLOCKS * NTHREADS) {

        ulonglong2 hh[16], rr[16];
        const ulonglong2* hp = reinterpret_cast<const ulonglong2*>(features + (size_t)n * 64);
        const ulonglong2* rp = reinterpret_cast<const ulonglong2*>(g_reduced + (size_t)n * 64);
#pragma unroll
        for (int q = 0; q < 16; q++) { hh[q] = hp[q]; rr[q] = rp[q]; }

        ull oacc[8];
        const ulonglong2* bo = reinterpret_cast<const ulonglong2*>(sbout);
#pragma unroll
        for (int i = 0; i < 4; i++) {
            ulonglong2 v = bo[i];
            oacc[2 * i] = v.x; oacc[2 * i + 1] = v.y;
        }

#pragma unroll 1
        for (int jq = 0; jq < 16; jq++) {
#pragma unroll
            for (int dj = 0; dj < 4; dj++) {
                int j = jq * 4 + dj;
                ull air = 0, aiz = 0, ain = 0, ahr = 0, ahz = 0, ahn = 0;
                const ulonglong2* wir = reinterpret_cast<const ulonglong2*>(sWih + (j      ) * 64);
                const ulonglong2* wiz = reinterpret_cast<const ulonglong2*>(sWih + (64  + j) * 64);
                const ulonglong2* win = reinterpret_cast<const ulonglong2*>(sWih + (128 + j) * 64);
                const ulonglong2* whr = reinterpret_cast<const ulonglong2*>(sWhh + (j      ) * 64);
                const ulonglong2* whz = reinterpret_cast<const ulonglong2*>(sWhh + (64  + j) * 64);
                const ulonglong2* whn = reinterpret_cast<const ulonglong2*>(sWhh + (128 + j) * 64);
#pragma unroll
                for (int q = 0; q < 16; q++) {
                    ulonglong2 rv = rr[q], hv = hh[q], wv;
                    wv = wir[q]; fma2(air, wv.x, rv.x); fma2(air, wv.y, rv.y);
                    wv = wiz[q]; fma2(aiz, wv.x, rv.x); fma2(aiz, wv.y, rv.y);
                    wv = win[q]; fma2(ain, wv.x, rv.x); fma2(ain, wv.y, rv.y);
                    wv = whr[q]; fma2(ahr, wv.x, hv.x); fma2(ahr, wv.y, hv.y);
                    wv = whz[q]; fma2(ahz, wv.x, hv.x); fma2(ahz, wv.y, hv.y);
                    wv = whn[q]; fma2(ahn, wv.x, hv.x); fma2(ahn, wv.y, hv.y);
                }
                float2 v;
                v = asf2(air); float ir  = v.x + v.y + sbih[j];
                v = asf2(aiz); float iz  = v.x + v.y + sbih[64 + j];
                v = asf2(ain); float inn = v.x + v.y + sbih[128 + j];
                v = asf2(ahr); float hr  = v.x + v.y + sbhh[j];
                v = asf2(ahz); float hz  = v.x + v.y + sbhh[64 + j];
                v = asf2(ahn); float hn  = v.x + v.y + sbhh[128 + j];
                float rg = sigm(ir + hr);
                float zg = sigm(iz + hz);
                float ng = tanhf(inn + rg * hn);
                float2 hjp = asf2((dj & 2) ? hh[jq].y : hh[jq].x);
                float hj = (dj & 1) ? hjp.y : hjp.x;
                float hnew = (1.f - zg) * ng + zg * hj;
                ull hn2;
                asm("mov.b64 %0, {%1, %1};" : "=l"(hn2) : "f"(hnew));
                const ulonglong2* wo = reinterpret_cast<const ulonglong2*>(sWoT + j * CC);
#pragma unroll
                for (int c = 0; c < 4; c++) {
                    ulonglong2 wv = wo[c];
                    fma2(oacc[2 * c], wv.x, hn2);
                    fma2(oacc[2 * c + 1], wv.y, hn2);
                }
            }
        }

        ulonglong2* op = reinterpret_cast<ulonglong2*>(out + (size_t)n * CC);
#pragma unroll
        for (int i = 0; i < 4; i++) {
            ulonglong2 v;
            v.x = oacc[2 * i]; v.y = oacc[2 * i + 1];
            op[i] = v;
        }
    }
}

// ---------------------------------------------------------------------------
extern "C" void kernel_launch(void* const* d_in, const int* in_sizes, int n_in,
                              void* d_out, int out_size) {
    const float* features = (const float*)d_in[0];
    const float* edge_emb = (const float*)d_in[1];
    const float* W_ih     = (const float*)d_in[2];
    const float* W_hh     = (const float*)d_in[3];
    const float* b_ih     = (const float*)d_in[4];
    const float* b_hh     = (const float*)d_in[5];
    const float* W_out    = (const float*)d_in[6];
    const float* b_out    = (const float*)d_in[7];
    const int*   etype    = (const int*)d_in[8];
    const int*   src      = (const int*)d_in[9];
    const int*   dst      = (const int*)d_in[10];
    float*       out      = (float*)d_out;

    cudaFuncSetAttribute(node_kernel, cudaFuncAttributeMaxDynamicSharedMemorySize, NODE_SMEM);

    zero_kernel<<<(NN * MSGD / 4 + 255) / 256, 256>>>();
    hist_kernel<<<(EE + 511) / 512, 512>>>(etype);
    scatter_kernel<<<(EE + 511) / 512, 512>>>(etype, src, dst);
    edge_kernel<<<EBLOCKS, ETHREADS>>>(features, edge_emb);
    node_kernel<<<NBLOCKS, NTHREADS, NODE_SMEM>>>(features, W_ih, W_hh,
                                                  b_ih, b_hh, W_out, b_out, out);
}